// round 12
// baseline (speedup 1.0000x reference)
#include <cuda_runtime.h>
#include <cstdint>

// ---------------------------------------------------------------------------
// StockModel: T=4, N=500, E=16, K=32, H=32, D=768, ZD=800, EH=200
//
//  K1  k_front: blocks 0..62  : price LSTM (8 warps/blk, warp/stock)
//               block  63     : packs W1a -> d_w1p, Wih2a -> d_wihp
//               blocks 64..255: GEMM GP = node_embs @ [W1b|Wih2b]
//  K2  k_attn:  vertex-conv attention -> d_alpha (cp.async pipeline, FFMA2)
//  K3  k_edge2: per (t,n): fused gather+vc, scores (f32x2), att,
//               hgX = att·P + Wih2a@hgv  -> d_hgX
//  K4  k_lstm2: gates = hgX + Whh2·h -> h_n -> out (N,2)
// ---------------------------------------------------------------------------

#define TT 4
#define NS 500
#define EE 16
#define KK 32
#define HH 32
#define DD 768
#define ZDIM 800
#define GPW 328
#define TN 2000
#define NROWS (TN * EE)

__device__ float d_pseq[TN * HH];
__device__ float d_GP[TN * GPW];
__device__ float d_alpha[NROWS * KK];
__device__ float d_hgX[TN * 128];
__device__ float d_w1p[32 * 200];    // W1[:, :32] pair-packed
__device__ float d_wihp[32 * 128];   // Wih2[:, :32] transposed: [l][g]

__device__ __forceinline__ float sigf(float x) { return 1.0f / (1.0f + __expf(-x)); }

// ---- packed f32x2 helpers (sm_100+) ----
__device__ __forceinline__ uint64_t pk2(float lo, float hi) {
    uint64_t r; asm("mov.b64 %0, {%1, %2};" : "=l"(r) : "f"(lo), "f"(hi)); return r;
}
__device__ __forceinline__ void ffma2(uint64_t& d, uint64_t a, uint64_t b) {
    asm("fma.rn.f32x2 %0, %1, %2, %3;" : "=l"(d) : "l"(a), "l"(b), "l"(d));
}
__device__ __forceinline__ float hadd2(uint64_t v) {
    float lo, hi; asm("mov.b64 {%0, %1}, %2;" : "=f"(lo), "=f"(hi) : "l"(v));
    return lo + hi;
}

// ---- cp.async helpers ----
__device__ __forceinline__ void cp16(uint32_t dst, const void* src) {
    asm volatile("cp.async.cg.shared.global [%0], [%1], 16;" :: "r"(dst), "l"(src) : "memory");
}
__device__ __forceinline__ void cp_commit() { asm volatile("cp.async.commit_group;" ::: "memory"); }
template<int N> __device__ __forceinline__ void cp_wait() {
    asm volatile("cp.async.wait_group %0;" :: "n"(N) : "memory");
}

// ===========================================================================
// K1: fused front: LSTM1 (blocks 0..62), packs (63), GEMM (64..255).
// dyn smem: lstm1 uses 4224 floats; gemm uses 2048.
// ===========================================================================
__global__ __launch_bounds__(256) void k_front(
    const float* __restrict__ prices,
    const float* __restrict__ Wih, const float* __restrict__ Whh,
    const float* __restrict__ bih, const float* __restrict__ bhh,
    const float* __restrict__ W1,
    const float* __restrict__ ne,
    const float* __restrict__ Wih2)
{
    extern __shared__ float dyn[];
    int tid = threadIdx.x;

    if (blockIdx.x < 63) {
        // ---------------- price LSTM: warp per stock ----------------
        float* whs = dyn;   // 128*33
        for (int idx = tid; idx < 4096; idx += 256)
            whs[(idx >> 5) * 33 + (idx & 31)] = Whh[idx];
        __syncthreads();

        int warp = blockIdx.x * 8 + (tid >> 5);
        int lane = tid & 31;
        if (warp >= NS) return;
        int n = warp;

        float wxi = Wih[lane],      wxf = Wih[32 + lane];
        float wxg = Wih[64 + lane], wxo = Wih[96 + lane];
        float bi = bih[lane]      + bhh[lane];
        float bf = bih[32 + lane] + bhh[32 + lane];
        float bg = bih[64 + lane] + bhh[64 + lane];
        float bo = bih[96 + lane] + bhh[96 + lane];

        float whi[32], whf[32], whg[32], who[32];
#pragma unroll
        for (int l = 0; l < 32; l++) {
            whi[l] = whs[lane * 33 + l];
            whf[l] = whs[(32 + lane) * 33 + l];
            whg[l] = whs[(64 + lane) * 33 + l];
            who[l] = whs[(96 + lane) * 33 + l];
        }

        float h = 0.0f, c = 0.0f;
#pragma unroll
        for (int t = 0; t < TT; t++) {
            float x = prices[t * NS + n];
            float zi = fmaf(wxi, x, bi), zf = fmaf(wxf, x, bf);
            float zg = fmaf(wxg, x, bg), zo = fmaf(wxo, x, bo);
#pragma unroll
            for (int l = 0; l < 32; l++) {
                float hl = __shfl_sync(0xffffffffu, h, l);
                zi = fmaf(whi[l], hl, zi);
                zf = fmaf(whf[l], hl, zf);
                zg = fmaf(whg[l], hl, zg);
                zo = fmaf(who[l], hl, zo);
            }
            c = sigf(zf) * c + sigf(zi) * tanhf(zg);
            h = sigf(zo) * tanhf(c);
            d_pseq[(t * NS + n) * HH + lane] = h;
        }
    } else if (blockIdx.x == 63) {
        // ---------------- weight packs ----------------
        for (int idx = tid; idx < 6400; idx += 256) {
            int pairIdx = idx >> 1, c = idx & 1;
            int d2 = pairIdx / 200, m = pairIdx % 200;
            d_w1p[idx] = W1[m * ZDIM + 2 * d2 + c];
        }
        for (int idx = tid; idx < 4096; idx += 256) {
            int l = idx >> 7, g = idx & 127;
            d_wihp[idx] = Wih2[g * ZDIM + l];
        }
    } else {
        // ---------------- GEMM: GP = ne(2000x768) @ B(768x328) ----------------
        float* As = dyn;          // 16*64
        float* Bs = dyn + 1024;   // 16*64
        int bx = blockIdx.x - 64;
        int rb = (bx & 31) * 64, cb2 = (bx >> 5) * 64;
        int tx = tid & 15, ty = tid >> 4;
        int lm = tid >> 2;
        int lk = (tid & 3) * 4;

        float acc[4][4];
#pragma unroll
        for (int r = 0; r < 4; r++)
#pragma unroll
            for (int cq = 0; cq < 4; cq++) acc[r][cq] = 0.0f;

        int arow = rb + lm;
        int bcol = cb2 + lm;

        for (int k0 = 0; k0 < DD; k0 += 16) {
            float4 av = make_float4(0.f, 0.f, 0.f, 0.f);
            if (arow < TN) av = *(const float4*)(ne + arow * DD + k0 + lk);
            float4 bv = make_float4(0.f, 0.f, 0.f, 0.f);
            if (bcol < 200)      bv = *(const float4*)(W1 + bcol * ZDIM + 32 + k0 + lk);
            else if (bcol < GPW) bv = *(const float4*)(Wih2 + (bcol - 200) * ZDIM + 32 + k0 + lk);
            As[(lk + 0) * 64 + lm] = av.x; As[(lk + 1) * 64 + lm] = av.y;
            As[(lk + 2) * 64 + lm] = av.z; As[(lk + 3) * 64 + lm] = av.w;
            Bs[(lk + 0) * 64 + lm] = bv.x; Bs[(lk + 1) * 64 + lm] = bv.y;
            Bs[(lk + 2) * 64 + lm] = bv.z; Bs[(lk + 3) * 64 + lm] = bv.w;
            __syncthreads();
#pragma unroll
            for (int k = 0; k < 16; k++) {
                float4 a4 = *(const float4*)(&As[k * 64 + ty * 4]);
                float4 b4 = *(const float4*)(&Bs[k * 64 + tx * 4]);
                float ar[4] = {a4.x, a4.y, a4.z, a4.w};
                float br[4] = {b4.x, b4.y, b4.z, b4.w};
#pragma unroll
                for (int r = 0; r < 4; r++)
#pragma unroll
                    for (int cq = 0; cq < 4; cq++)
                        acc[r][cq] = fmaf(ar[r], br[cq], acc[r][cq]);
            }
            __syncthreads();
        }
#pragma unroll
        for (int r = 0; r < 4; r++) {
            int rrow = rb + ty * 4 + r;
            int col = cb2 + tx * 4;
            if (rrow < TN && col < GPW) {
                float4 v = make_float4(acc[r][0], acc[r][1], acc[r][2], acc[r][3]);
                *(float4*)(d_GP + rrow * GPW + col) = v;
            }
        }
    }
}

// ===========================================================================
// K2: vertex-conv attention only. 500 blocks x 256 threads.
// cp.async double-buffered member-row pipeline, FFMA2 math.
// ===========================================================================
#define AT2_WT    0        // 4096  wt[q][j][d]
#define AT2_BT    4096     // 1024
#define AT2_WK    5120     // 32
#define AT2_ADJ   5152     // 64 ints
#define AT2_TN    5216     // 64 ints
#define AT2_MIDX  5280     // 2048 ints
#define AT2_SROWS 7328     // 2 x 256 x 36 = 18432
#define AT2_TOTAL 25760    // = 103040 bytes

__global__ __launch_bounds__(256) void k_attn(
    const int* __restrict__ adj, const int* __restrict__ mem,
    const float* __restrict__ Wt, const float* __restrict__ bt,
    const float* __restrict__ wk)
{
    extern __shared__ float dyn[];
    int tid = threadIdx.x;

    float* btA   = dyn + AT2_BT;
    float* wkA   = dyn + AT2_WK;
    int*   sadj  = (int*)(dyn + AT2_ADJ);
    int*   stN   = (int*)(dyn + AT2_TN);
    int*   midx  = (int*)(dyn + AT2_MIDX);
    uint32_t sbase = (uint32_t)__cvta_generic_to_shared(dyn);

    int rloc = tid & 63, q = tid >> 6;
    int w = tid >> 5, lane = tid & 31;
    int cg = lane >> 3, cb = lane & 7;

    if (tid < 64) {
        int row = blockIdx.x * 64 + tid;
        int tn = row >> 4, e = row & 15;
        sadj[tid] = adj[tn * EE + e];
        stN[tid]  = (tn / NS) * NS;
    }
    for (int idx = tid; idx < 1024; idx += 256) btA[idx] = bt[idx];
    if (tid < 32) wkA[tid] = wk[tid];
    __syncthreads();
    for (int idx = tid; idx < 2048; idx += 256) {
        int r = idx >> 5, i = idx & 31;
        midx[idx] = stN[r] + mem[(stN[r] + sadj[r]) * KK + i];
    }
    __syncthreads();

    // prologue: stage srows for step 0 into buffer 0
    {
#pragma unroll
        for (int rr = 0; rr < 8; rr++) {
            int r = w * 32 + rr * 4 + cg;
            int rl = r & 63, qq2 = r >> 6;
            int mrow = midx[rl * 32 + 8 * qq2];     // s = 0
            cp16(sbase + (AT2_SROWS + r * 36 + cb * 4) * 4,
                 d_pseq + mrow * 32 + cb * 4);
        }
        cp_commit();
    }

    float acc[32];
#pragma unroll
    for (int j = 0; j < 32; j++) acc[j] = 0.0f;

    for (int s = 0; s < 8; s++) {
        int i = 8 * q + s;
        // wt(s): synchronous group (L2-resident, cheap)
        {
            const float* wsrc = Wt + i * 1024 + rloc * 16;
            uint32_t wd = sbase + (AT2_WT + q * 1024 + rloc * 16) * 4;
            cp16(wd, wsrc); cp16(wd + 16, wsrc + 4);
            cp16(wd + 32, wsrc + 8); cp16(wd + 48, wsrc + 12);
            cp_commit();
        }
        // srows(s+1): pipelined group
        if (s < 7) {
            int bsel = (s + 1) & 1;
#pragma unroll
            for (int rr = 0; rr < 8; rr++) {
                int r = w * 32 + rr * 4 + cg;
                int rl = r & 63, qq2 = r >> 6;
                int mrow = midx[rl * 32 + 8 * qq2 + s + 1];
                cp16(sbase + (AT2_SROWS + bsel * 9216 + r * 36 + cb * 4) * 4,
                     d_pseq + mrow * 32 + cb * 4);
            }
            cp_commit();
            cp_wait<1>();
        } else {
            cp_wait<0>();
        }
        __syncthreads();

        uint64_t rgp[16];
        {
            const float4* basep =
                (const float4*)(dyn + AT2_SROWS + (s & 1) * 9216 + (q * 64 + rloc) * 36);
#pragma unroll
            for (int u = 0; u < 8; u++) {
                float4 rv = basep[u];
                rgp[2 * u]     = pk2(rv.x, rv.y);
                rgp[2 * u + 1] = pk2(rv.z, rv.w);
            }
        }
        const float* wb = dyn + AT2_WT + q * 1024;
        float em[32];
        float srow = 0.0f;
#pragma unroll
        for (int j = 0; j < 32; j++) {
            const ulonglong2* w2p = (const ulonglong2*)(wb + j * 32);
            uint64_t mac = pk2(btA[i * 32 + j], 0.0f);
#pragma unroll
            for (int u = 0; u < 8; u++) {
                ulonglong2 wv = w2p[u];
                ffma2(mac, wv.x, rgp[2 * u]);
                ffma2(mac, wv.y, rgp[2 * u + 1]);
            }
            float ev = __expf(hadd2(mac));
            em[j] = ev;
            srow += ev;
        }
        float f = __fdividef(wkA[i], srow);
#pragma unroll
        for (int j = 0; j < 32; j++) acc[j] = fmaf(em[j], f, acc[j]);
        __syncthreads();
    }

    // cross-quarter reduction (red overlays srows)
    float* red = dyn + AT2_SROWS;
    {
        float4* rp = (float4*)(red + q * 2048 + rloc * 32);
#pragma unroll
        for (int u = 0; u < 8; u++)
            rp[u] = make_float4(acc[u * 4], acc[u * 4 + 1], acc[u * 4 + 2], acc[u * 4 + 3]);
    }
    __syncthreads();
    for (int o = tid; o < 512; o += 256) {
        const float4 v0 = *(const float4*)(red + o * 4);
        const float4 v1 = *(const float4*)(red + 2048 + o * 4);
        const float4 v2 = *(const float4*)(red + 4096 + o * 4);
        const float4 v3 = *(const float4*)(red + 6144 + o * 4);
        float4 v = make_float4(v0.x + v1.x + v2.x + v3.x,
                               v0.y + v1.y + v2.y + v3.y,
                               v0.z + v1.z + v2.z + v3.z,
                               v0.w + v1.w + v2.w + v3.w);
        *(float4*)(d_alpha + blockIdx.x * 2048 + o * 4) = v;
    }
}

// ===========================================================================
// K3: per (t,n): fused gather+vc, scores (f32x2), att, hgX. smem 50KB.
// ===========================================================================
#define E_W1P    0         // 6400
#define E_WIHP   6400      // 4096
#define E_ALPHA  10496     // 512
#define E_VC     11008     // 512
#define E_B1S    11520     // 200
#define E_W2S    11720     // 200
#define E_SVALS  11920     // 16
#define E_SATT   11936     // 16
#define E_HGV    11952     // 32
#define E_SADJ   11984     // 16 ints
#define E_MIDX   12000     // 512 ints
#define E_TOTAL  12512     // floats = 50048 B

__global__ __launch_bounds__(256) void k_edge2(
    const int* __restrict__ adj, const int* __restrict__ mem,
    const float* __restrict__ bk,
    const float* __restrict__ b1,
    const float* __restrict__ W2, const float* __restrict__ b2)
{
    extern __shared__ float sm[];
    float* w1p    = sm + E_W1P;
    float* wihp   = sm + E_WIHP;
    float* alpha  = sm + E_ALPHA;
    float* vc     = sm + E_VC;
    float* b1s    = sm + E_B1S;
    float* w2s    = sm + E_W2S;
    float* svals  = sm + E_SVALS;
    float* satt   = sm + E_SATT;
    float* hgv_s  = sm + E_HGV;
    int*   sadj   = (int*)(sm + E_SADJ);
    int*   midx   = (int*)(sm + E_MIDX);

    int tid = threadIdx.x, w = tid >> 5, lane = tid & 31;
    int bid = blockIdx.x;
    int tN  = (bid / NS) * NS;

    if (tid < EE) sadj[tid] = adj[bid * EE + tid];
    for (int q = tid; q < 512; q += 256) alpha[q] = d_alpha[bid * 512 + q];
    {
        const float4* src = (const float4*)d_w1p;
        float4* dst = (float4*)w1p;
        for (int idx = tid; idx < 1600; idx += 256) dst[idx] = src[idx];
        const float4* src2 = (const float4*)d_wihp;
        float4* dst2 = (float4*)wihp;
        for (int idx = tid; idx < 1024; idx += 256) dst2[idx] = src2[idx];
    }
    if (tid < 200) { b1s[tid] = b1[tid]; w2s[tid] = W2[tid]; }
    __syncthreads();

    for (int q = tid; q < EE * KK; q += 256)
        midx[q] = tN + mem[(tN + sadj[q >> 5]) * KK + (q & 31)];
    __syncthreads();

    // fused gather + vc: warp w handles edges {w, w+8}; lane = d
    float bk0 = __ldg(bk);
#pragma unroll
    for (int eo = 0; eo < 2; eo++) {
        int e = w + eo * 8;
        float acc = bk0;
#pragma unroll
        for (int j = 0; j < 32; j++) {
            int row = midx[e * 32 + j];
            float a = alpha[e * 32 + j];
            acc = fmaf(a, d_pseq[row * 32 + lane], acc);
        }
        vc[e * 32 + lane] = acc;
    }
    __syncthreads();

    // ---- edge scores: 16 threads/edge; packed f32x2 over d ----
    {
        int e = tid >> 4, q = tid & 15;
        uint64_t vp[16];
#pragma unroll
        for (int d2 = 0; d2 < 16; d2++)
            vp[d2] = pk2(vc[e * 32 + 2 * d2], vc[e * 32 + 2 * d2 + 1]);
        const float* Grow = d_GP + (tN + sadj[e]) * GPW;
        const uint64_t* w1p64 = (const uint64_t*)w1p;
        float partial = 0.0f;
        for (int m = q; m < 200; m += 16) {
            uint64_t mac = pk2(b1s[m] + Grow[m], 0.0f);
#pragma unroll
            for (int d2 = 0; d2 < 16; d2++)
                ffma2(mac, vp[d2], w1p64[d2 * 200 + m]);
            partial = fmaf(w2s[m], fmaxf(hadd2(mac), 0.0f), partial);
        }
#pragma unroll
        for (int off = 8; off > 0; off >>= 1)
            partial += __shfl_xor_sync(0xffffffffu, partial, off);
        if (q == 0) svals[e] = partial + __ldg(b2);
    }
    __syncthreads();

    if (tid == 0) {
        float mx = svals[0];
#pragma unroll
        for (int e = 1; e < EE; e++) mx = fmaxf(mx, svals[e]);
        float s = 0.0f;
#pragma unroll
        for (int e = 0; e < EE; e++) { float v = __expf(svals[e] - mx); satt[e] = v; s += v; }
        float inv = 1.0f / s;
#pragma unroll
        for (int e = 0; e < EE; e++) satt[e] *= inv;
    }
    __syncthreads();

    if (tid < 32) {
        float acc = 0.0f;
#pragma unroll
        for (int e = 0; e < EE; e++) acc = fmaf(satt[e], vc[e * 32 + tid], acc);
        hgv_s[tid] = acc;
    }
    __syncthreads();

    // hgX[g] = sum_e att_e * P[t,a_e,g] + sum_l wihp[l][g] * hgv[l]
    if (tid < 128) {
        int g = tid;
        float acc = 0.0f;
#pragma unroll
        for (int e = 0; e < EE; e++)
            acc = fmaf(satt[e], d_GP[(tN + sadj[e]) * GPW + 200 + g], acc);
#pragma unroll
        for (int l = 0; l < 32; l++)
            acc = fmaf(wihp[l * 128 + g], hgv_s[l], acc);
        d_hgX[bid * 128 + g] = acc;
    }
}

// ===========================================================================
// K4: second LSTM + heads. Input gates precomputed in hgX.
// ===========================================================================
__global__ __launch_bounds__(128) void k_lstm2(
    const float* __restrict__ Whh2,
    const float* __restrict__ bih2, const float* __restrict__ bhh2,
    const float* __restrict__ Wf1, const float* __restrict__ bf1,
    const float* __restrict__ Wf2, const float* __restrict__ bf2,
    float* __restrict__ out)
{
    __shared__ float whs[128 * 33];
    int tid = threadIdx.x;
    for (int idx = tid; idx < 4096; idx += 128)
        whs[(idx >> 5) * 33 + (idx & 31)] = Whh2[idx];
    __syncthreads();

    int warp = (blockIdx.x * blockDim.x + tid) >> 5;
    int lane = tid & 31;
    if (warp >= NS) return;
    int n = warp;

    float bi = bih2[lane]      + bhh2[lane];
    float bf = bih2[32 + lane] + bhh2[32 + lane];
    float bg = bih2[64 + lane] + bhh2[64 + lane];
    float bo = bih2[96 + lane] + bhh2[96 + lane];

    float whi[32], whf[32], whg[32], who[32];
#pragma unroll
    for (int l = 0; l < 32; l++) {
        whi[l] = whs[lane * 33 + l];
        whf[l] = whs[(32 + lane) * 33 + l];
        whg[l] = whs[(64 + lane) * 33 + l];
        who[l] = whs[(96 + lane) * 33 + l];
    }

    float h = 0.0f, c = 0.0f;
#pragma unroll
    for (int t = 0; t < TT; t++) {
        const float* hx = d_hgX + (t * NS + n) * 128;
        float zi = bi + hx[lane];
        float zf = bf + hx[32 + lane];
        float zg = bg + hx[64 + lane];
        float zo = bo + hx[96 + lane];
#pragma unroll
        for (int l = 0; l < 32; l++) {
            float hl = __shfl_sync(0xffffffffu, h, l);
            zi = fmaf(whi[l], hl, zi);
            zf = fmaf(whf[l], hl, zf);
            zg = fmaf(whg[l], hl, zg);
            zo = fmaf(who[l], hl, zo);
        }
        c = sigf(zf) * c + sigf(zi) * tanhf(zg);
        h = sigf(zo) * tanhf(c);
    }

    float f1a = bf1[lane], f1b = bf1[32 + lane];
#pragma unroll
    for (int l = 0; l < 32; l++) {
        float hl = __shfl_sync(0xffffffffu, h, l);
        f1a = fmaf(Wf1[lane * 32 + l], hl, f1a);
        f1b = fmaf(Wf1[(32 + lane) * 32 + l], hl, f1b);
    }
    float p0 = Wf2[lane] * f1a + Wf2[32 + lane] * f1b;
    float p1 = Wf2[64 + lane] * f1a + Wf2[96 + lane] * f1b;
#pragma unroll
    for (int off = 16; off > 0; off >>= 1) {
        p0 += __shfl_xor_sync(0xffffffffu, p0, off);
        p1 += __shfl_xor_sync(0xffffffffu, p1, off);
    }
    if (lane == 0) {
        out[n * 2]     = p0 + bf2[0];
        out[n * 2 + 1] = p1 + bf2[1];
    }
}

// ===========================================================================
extern "C" void kernel_launch(void* const* d_in, const int* in_sizes, int n_in,
                              void* d_out, int out_size)
{
    const float* prices    = (const float*)d_in[0];
    const float* node_embs = (const float*)d_in[1];
    const int*   adj       = (const int*)  d_in[2];
    const int*   mem       = (const int*)  d_in[3];
    const float* W_ih1 = (const float*)d_in[4];
    const float* W_hh1 = (const float*)d_in[5];
    const float* b_ih1 = (const float*)d_in[6];
    const float* b_hh1 = (const float*)d_in[7];
    const float* Wt    = (const float*)d_in[8];
    const float* bt    = (const float*)d_in[9];
    const float* wk    = (const float*)d_in[10];
    const float* bk    = (const float*)d_in[11];
    const float* W1    = (const float*)d_in[12];
    const float* b1    = (const float*)d_in[13];
    const float* W2    = (const float*)d_in[14];
    const float* b2    = (const float*)d_in[15];
    const float* W_ih2 = (const float*)d_in[16];
    const float* W_hh2 = (const float*)d_in[17];
    const float* b_ih2 = (const float*)d_in[18];
    const float* b_hh2 = (const float*)d_in[19];
    const float* Wf1   = (const float*)d_in[20];
    const float* bf1   = (const float*)d_in[21];
    const float* Wf2   = (const float*)d_in[22];
    const float* bf2   = (const float*)d_in[23];
    float* out = (float*)d_out;

    const int front_smem = 4224 * 4;      // max(lstm1 4224, gemm 2048) floats
    const int attn_smem  = AT2_TOTAL * 4; // 103040 B -> 2 blocks/SM
    const int edge_smem  = E_TOTAL * 4;   // 50048 B  -> 4 blocks/SM
    cudaFuncSetAttribute(k_attn,  cudaFuncAttributeMaxDynamicSharedMemorySize, attn_smem);
    cudaFuncSetAttribute(k_edge2, cudaFuncAttributeMaxDynamicSharedMemorySize, edge_smem);

    k_front<<<256, 256, front_smem>>>(prices, W_ih1, W_hh1, b_ih1, b_hh1,
                                      W1, node_embs, W_ih2);
    k_attn<<<NROWS / 64, 256, attn_smem>>>(adj, mem, Wt, bt, wk);
    k_edge2<<<TN, 256, edge_smem>>>(adj, mem, bk, b1, W2, b2);
    k_lstm2<<<125, 128>>>(W_hh2, b_ih2, b_hh2, Wf1, bf1, Wf2, bf2, out);
}

// round 13
// speedup vs baseline: 1.3274x; 1.3274x over previous
#include <cuda_runtime.h>
#include <cstdint>

// ---------------------------------------------------------------------------
// StockModel: T=4, N=500, E=16, K=32, H=32, D=768, ZD=800, EH=200
//
//  K1  k_lstm1: prices -> p_seq; block 125 packs W1a -> d_w1p, Wih2a -> d_wihp
//  K2  k_mid2:  blocks [0,500): vertex-conv attention -> d_alpha
//               (cp.async pipeline, FFMA2, __launch_bounds__(256,2))
//               blocks [500,692): GEMM GP = node_embs @ [W1b|Wih2b]
//  K3  k_edge2: per (t,n): fused gather+vc, scores (f32x2), att,
//               hgX = att*P + Wih2a@hgv -> d_hgX   (__launch_bounds__(256,4))
//  K4  k_lstm2: gates = hgX + Whh2*h -> h_n -> out (N,2)
// ---------------------------------------------------------------------------

#define TT 4
#define NS 500
#define EE 16
#define KK 32
#define HH 32
#define DD 768
#define ZDIM 800
#define GPW 328
#define TN 2000
#define NROWS (TN * EE)

__device__ float d_pseq[TN * HH];
__device__ float d_GP[TN * GPW];
__device__ float d_alpha[NROWS * KK];
__device__ float d_hgX[TN * 128];
__device__ float d_w1p[32 * 200];    // W1[:, :32] pair-packed
__device__ float d_wihp[32 * 128];   // Wih2[:, :32] transposed: [l][g]

__device__ __forceinline__ float sigf(float x) { return 1.0f / (1.0f + __expf(-x)); }

// ---- packed f32x2 helpers (sm_100+) ----
__device__ __forceinline__ uint64_t pk2(float lo, float hi) {
    uint64_t r; asm("mov.b64 %0, {%1, %2};" : "=l"(r) : "f"(lo), "f"(hi)); return r;
}
__device__ __forceinline__ void ffma2(uint64_t& d, uint64_t a, uint64_t b) {
    asm("fma.rn.f32x2 %0, %1, %2, %3;" : "=l"(d) : "l"(a), "l"(b), "l"(d));
}
__device__ __forceinline__ float hadd2(uint64_t v) {
    float lo, hi; asm("mov.b64 {%0, %1}, %2;" : "=f"(lo), "=f"(hi) : "l"(v));
    return lo + hi;
}

// ---- cp.async helpers ----
__device__ __forceinline__ void cp16(uint32_t dst, const void* src) {
    asm volatile("cp.async.cg.shared.global [%0], [%1], 16;" :: "r"(dst), "l"(src) : "memory");
}
__device__ __forceinline__ void cp_commit() { asm volatile("cp.async.commit_group;" ::: "memory"); }
template<int N> __device__ __forceinline__ void cp_wait() {
    asm volatile("cp.async.wait_group %0;" :: "n"(N) : "memory");
}

// ===========================================================================
// K1: price LSTM (blocks 0..124), weight packs (block 125).
// ===========================================================================
__global__ __launch_bounds__(128) void k_lstm1(
    const float* __restrict__ prices,
    const float* __restrict__ Wih, const float* __restrict__ Whh,
    const float* __restrict__ bih, const float* __restrict__ bhh,
    const float* __restrict__ W1, const float* __restrict__ Wih2)
{
    int tid = threadIdx.x;
    if (blockIdx.x == 125) {
        for (int idx = tid; idx < 6400; idx += 128) {
            int pairIdx = idx >> 1, c = idx & 1;
            int d2 = pairIdx / 200, m = pairIdx % 200;
            d_w1p[idx] = W1[m * ZDIM + 2 * d2 + c];
        }
        for (int idx = tid; idx < 4096; idx += 128) {
            int l = idx >> 7, g = idx & 127;
            d_wihp[idx] = Wih2[g * ZDIM + l];
        }
        return;
    }

    __shared__ float whs[128 * 33];
    for (int idx = tid; idx < 4096; idx += 128)
        whs[(idx >> 5) * 33 + (idx & 31)] = Whh[idx];
    __syncthreads();

    int warp = (blockIdx.x * blockDim.x + tid) >> 5;
    int lane = tid & 31;
    if (warp >= NS) return;
    int n = warp;

    float wxi = Wih[lane],      wxf = Wih[32 + lane];
    float wxg = Wih[64 + lane], wxo = Wih[96 + lane];
    float bi = bih[lane]      + bhh[lane];
    float bf = bih[32 + lane] + bhh[32 + lane];
    float bg = bih[64 + lane] + bhh[64 + lane];
    float bo = bih[96 + lane] + bhh[96 + lane];

    float whi[32], whf[32], whg[32], who[32];
#pragma unroll
    for (int l = 0; l < 32; l++) {
        whi[l] = whs[lane * 33 + l];
        whf[l] = whs[(32 + lane) * 33 + l];
        whg[l] = whs[(64 + lane) * 33 + l];
        who[l] = whs[(96 + lane) * 33 + l];
    }

    float h = 0.0f, c = 0.0f;
#pragma unroll
    for (int t = 0; t < TT; t++) {
        float x = prices[t * NS + n];
        float zi = fmaf(wxi, x, bi), zf = fmaf(wxf, x, bf);
        float zg = fmaf(wxg, x, bg), zo = fmaf(wxo, x, bo);
#pragma unroll
        for (int l = 0; l < 32; l++) {
            float hl = __shfl_sync(0xffffffffu, h, l);
            zi = fmaf(whi[l], hl, zi);
            zf = fmaf(whf[l], hl, zf);
            zg = fmaf(whg[l], hl, zg);
            zo = fmaf(who[l], hl, zo);
        }
        c = sigf(zf) * c + sigf(zi) * tanhf(zg);
        h = sigf(zo) * tanhf(c);
        d_pseq[(t * NS + n) * HH + lane] = h;
    }
}

// ===========================================================================
// K2: fused attn (blocks 0..499) + GEMM (blocks 500..691).
// __launch_bounds__(256, 2) pins 2 blocks/SM (128-reg cap).
// ===========================================================================
#define AT2_WT    0        // 4096  wt[q][j][d]
#define AT2_BT    4096     // 1024
#define AT2_WK    5120     // 32
#define AT2_ADJ   5152     // 64 ints
#define AT2_TN    5216     // 64 ints
#define AT2_MIDX  5280     // 2048 ints
#define AT2_SROWS 7328     // 2 x 256 x 36 = 18432
#define AT2_TOTAL 25760    // = 103040 bytes
#define ATTN_BLKS 500

__global__ __launch_bounds__(256, 2) void k_mid2(
    const int* __restrict__ adj, const int* __restrict__ mem,
    const float* __restrict__ Wt, const float* __restrict__ bt,
    const float* __restrict__ wk,
    const float* __restrict__ ne,
    const float* __restrict__ W1,
    const float* __restrict__ Wih2)
{
    extern __shared__ float dyn[];
    int tid = threadIdx.x;

    if (blockIdx.x < ATTN_BLKS) {
        float* btA   = dyn + AT2_BT;
        float* wkA   = dyn + AT2_WK;
        int*   sadj  = (int*)(dyn + AT2_ADJ);
        int*   stN   = (int*)(dyn + AT2_TN);
        int*   midx  = (int*)(dyn + AT2_MIDX);
        uint32_t sbase = (uint32_t)__cvta_generic_to_shared(dyn);

        int rloc = tid & 63, q = tid >> 6;
        int w = tid >> 5, lane = tid & 31;
        int cg = lane >> 3, cb = lane & 7;

        if (tid < 64) {
            int row = blockIdx.x * 64 + tid;
            int tn = row >> 4, e = row & 15;
            sadj[tid] = adj[tn * EE + e];
            stN[tid]  = (tn / NS) * NS;
        }
        for (int idx = tid; idx < 1024; idx += 256) btA[idx] = bt[idx];
        if (tid < 32) wkA[tid] = wk[tid];
        __syncthreads();
        for (int idx = tid; idx < 2048; idx += 256) {
            int r = idx >> 5, i = idx & 31;
            midx[idx] = stN[r] + mem[(stN[r] + sadj[r]) * KK + i];
        }
        __syncthreads();

        // prologue: stage srows for step 0 into buffer 0
        {
#pragma unroll
            for (int rr = 0; rr < 8; rr++) {
                int r = w * 32 + rr * 4 + cg;
                int rl = r & 63, qq2 = r >> 6;
                int mrow = midx[rl * 32 + 8 * qq2];
                cp16(sbase + (AT2_SROWS + r * 36 + cb * 4) * 4,
                     d_pseq + mrow * 32 + cb * 4);
            }
            cp_commit();
        }

        float acc[32];
#pragma unroll
        for (int j = 0; j < 32; j++) acc[j] = 0.0f;

        for (int s = 0; s < 8; s++) {
            int i = 8 * q + s;
            // wt(s): synchronous group (L2-resident, cheap)
            {
                const float* wsrc = Wt + i * 1024 + rloc * 16;
                uint32_t wd = sbase + (AT2_WT + q * 1024 + rloc * 16) * 4;
                cp16(wd, wsrc); cp16(wd + 16, wsrc + 4);
                cp16(wd + 32, wsrc + 8); cp16(wd + 48, wsrc + 12);
                cp_commit();
            }
            // srows(s+1): pipelined group
            if (s < 7) {
                int bsel = (s + 1) & 1;
#pragma unroll
                for (int rr = 0; rr < 8; rr++) {
                    int r = w * 32 + rr * 4 + cg;
                    int rl = r & 63, qq2 = r >> 6;
                    int mrow = midx[rl * 32 + 8 * qq2 + s + 1];
                    cp16(sbase + (AT2_SROWS + bsel * 9216 + r * 36 + cb * 4) * 4,
                         d_pseq + mrow * 32 + cb * 4);
                }
                cp_commit();
                cp_wait<1>();
            } else {
                cp_wait<0>();
            }
            __syncthreads();

            uint64_t rgp[16];
            {
                const float4* basep =
                    (const float4*)(dyn + AT2_SROWS + (s & 1) * 9216 + (q * 64 + rloc) * 36);
#pragma unroll
                for (int u = 0; u < 8; u++) {
                    float4 rv = basep[u];
                    rgp[2 * u]     = pk2(rv.x, rv.y);
                    rgp[2 * u + 1] = pk2(rv.z, rv.w);
                }
            }
            const float* wb = dyn + AT2_WT + q * 1024;
            float em[32];
            float srow = 0.0f;
#pragma unroll
            for (int j = 0; j < 32; j++) {
                const ulonglong2* w2p = (const ulonglong2*)(wb + j * 32);
                uint64_t mac = pk2(btA[i * 32 + j], 0.0f);
#pragma unroll
                for (int u = 0; u < 8; u++) {
                    ulonglong2 wv = w2p[u];
                    ffma2(mac, wv.x, rgp[2 * u]);
                    ffma2(mac, wv.y, rgp[2 * u + 1]);
                }
                float ev = __expf(hadd2(mac));   // |m| small: no max-subtraction needed
                em[j] = ev;
                srow += ev;
            }
            float f = __fdividef(wkA[i], srow);
#pragma unroll
            for (int j = 0; j < 32; j++) acc[j] = fmaf(em[j], f, acc[j]);
            __syncthreads();
        }

        // cross-quarter reduction (red overlays srows)
        float* red = dyn + AT2_SROWS;
        {
            float4* rp = (float4*)(red + q * 2048 + rloc * 32);
#pragma unroll
            for (int u = 0; u < 8; u++)
                rp[u] = make_float4(acc[u * 4], acc[u * 4 + 1], acc[u * 4 + 2], acc[u * 4 + 3]);
        }
        __syncthreads();
        for (int o = tid; o < 512; o += 256) {
            const float4 v0 = *(const float4*)(red + o * 4);
            const float4 v1 = *(const float4*)(red + 2048 + o * 4);
            const float4 v2 = *(const float4*)(red + 4096 + o * 4);
            const float4 v3 = *(const float4*)(red + 6144 + o * 4);
            float4 v = make_float4(v0.x + v1.x + v2.x + v3.x,
                                   v0.y + v1.y + v2.y + v3.y,
                                   v0.z + v1.z + v2.z + v3.z,
                                   v0.w + v1.w + v2.w + v3.w);
            *(float4*)(d_alpha + blockIdx.x * 2048 + o * 4) = v;
        }
    } else {
        // -------- GEMM part: GP = ne(2000x768) @ B(768x328) --------
        float* As = dyn;          // 16*64
        float* Bs = dyn + 1024;   // 16*64
        int bx = blockIdx.x - ATTN_BLKS;
        int rb = (bx & 31) * 64, cb2 = (bx >> 5) * 64;
        int tx = tid & 15, ty = tid >> 4;
        int lm = tid >> 2;
        int lk = (tid & 3) * 4;

        float acc[4][4];
#pragma unroll
        for (int r = 0; r < 4; r++)
#pragma unroll
            for (int cq = 0; cq < 4; cq++) acc[r][cq] = 0.0f;

        int arow = rb + lm;
        int bcol = cb2 + lm;

        for (int k0 = 0; k0 < DD; k0 += 16) {
            float4 av = make_float4(0.f, 0.f, 0.f, 0.f);
            if (arow < TN) av = *(const float4*)(ne + arow * DD + k0 + lk);
            float4 bv = make_float4(0.f, 0.f, 0.f, 0.f);
            if (bcol < 200)      bv = *(const float4*)(W1 + bcol * ZDIM + 32 + k0 + lk);
            else if (bcol < GPW) bv = *(const float4*)(Wih2 + (bcol - 200) * ZDIM + 32 + k0 + lk);
            As[(lk + 0) * 64 + lm] = av.x; As[(lk + 1) * 64 + lm] = av.y;
            As[(lk + 2) * 64 + lm] = av.z; As[(lk + 3) * 64 + lm] = av.w;
            Bs[(lk + 0) * 64 + lm] = bv.x; Bs[(lk + 1) * 64 + lm] = bv.y;
            Bs[(lk + 2) * 64 + lm] = bv.z; Bs[(lk + 3) * 64 + lm] = bv.w;
            __syncthreads();
#pragma unroll
            for (int k = 0; k < 16; k++) {
                float4 a4 = *(const float4*)(&As[k * 64 + ty * 4]);
                float4 b4 = *(const float4*)(&Bs[k * 64 + tx * 4]);
                float ar[4] = {a4.x, a4.y, a4.z, a4.w};
                float br[4] = {b4.x, b4.y, b4.z, b4.w};
#pragma unroll
                for (int r = 0; r < 4; r++)
#pragma unroll
                    for (int cq = 0; cq < 4; cq++)
                        acc[r][cq] = fmaf(ar[r], br[cq], acc[r][cq]);
            }
            __syncthreads();
        }
#pragma unroll
        for (int r = 0; r < 4; r++) {
            int rrow = rb + ty * 4 + r;
            int col = cb2 + tx * 4;
            if (rrow < TN && col < GPW) {
                float4 v = make_float4(acc[r][0], acc[r][1], acc[r][2], acc[r][3]);
                *(float4*)(d_GP + rrow * GPW + col) = v;
            }
        }
    }
}

// ===========================================================================
// K3: per (t,n): fused gather+vc, scores (f32x2), att, hgX. smem 50KB.
// __launch_bounds__(256, 4) pins 4 blocks/SM (64-reg cap).
// ===========================================================================
#define E_W1P    0         // 6400
#define E_WIHP   6400      // 4096
#define E_ALPHA  10496     // 512
#define E_VC     11008     // 512
#define E_B1S    11520     // 200
#define E_W2S    11720     // 200
#define E_SVALS  11920     // 16
#define E_SATT   11936     // 16
#define E_HGV    11952     // 32
#define E_SADJ   11984     // 16 ints
#define E_MIDX   12000     // 512 ints
#define E_TOTAL  12512     // floats = 50048 B

__global__ __launch_bounds__(256, 4) void k_edge2(
    const int* __restrict__ adj, const int* __restrict__ mem,
    const float* __restrict__ bk,
    const float* __restrict__ b1,
    const float* __restrict__ W2, const float* __restrict__ b2)
{
    extern __shared__ float sm[];
    float* w1p    = sm + E_W1P;
    float* wihp   = sm + E_WIHP;
    float* alpha  = sm + E_ALPHA;
    float* vc     = sm + E_VC;
    float* b1s    = sm + E_B1S;
    float* w2s    = sm + E_W2S;
    float* svals  = sm + E_SVALS;
    float* satt   = sm + E_SATT;
    float* hgv_s  = sm + E_HGV;
    int*   sadj   = (int*)(sm + E_SADJ);
    int*   midx   = (int*)(sm + E_MIDX);

    int tid = threadIdx.x, w = tid >> 5, lane = tid & 31;
    int bid = blockIdx.x;
    int tN  = (bid / NS) * NS;

    if (tid < EE) sadj[tid] = adj[bid * EE + tid];
    for (int q = tid; q < 512; q += 256) alpha[q] = d_alpha[bid * 512 + q];
    {
        const float4* src = (const float4*)d_w1p;
        float4* dst = (float4*)w1p;
        for (int idx = tid; idx < 1600; idx += 256) dst[idx] = src[idx];
        const float4* src2 = (const float4*)d_wihp;
        float4* dst2 = (float4*)wihp;
        for (int idx = tid; idx < 1024; idx += 256) dst2[idx] = src2[idx];
    }
    if (tid < 200) { b1s[tid] = b1[tid]; w2s[tid] = W2[tid]; }
    __syncthreads();

    for (int q = tid; q < EE * KK; q += 256)
        midx[q] = tN + mem[(tN + sadj[q >> 5]) * KK + (q & 31)];
    __syncthreads();

    // fused gather + vc: warp w handles edges {w, w+8}; lane = d
    float bk0 = __ldg(bk);
#pragma unroll
    for (int eo = 0; eo < 2; eo++) {
        int e = w + eo * 8;
        float acc = bk0;
#pragma unroll
        for (int j = 0; j < 32; j++) {
            int row = midx[e * 32 + j];
            float a = alpha[e * 32 + j];
            acc = fmaf(a, d_pseq[row * 32 + lane], acc);
        }
        vc[e * 32 + lane] = acc;
    }
    __syncthreads();

    // ---- edge scores: 16 threads/edge; packed f32x2 over d ----
    {
        int e = tid >> 4, q = tid & 15;
        uint64_t vp[16];
#pragma unroll
        for (int d2 = 0; d2 < 16; d2++)
            vp[d2] = pk2(vc[e * 32 + 2 * d2], vc[e * 32 + 2 * d2 + 1]);
        const float* Grow = d_GP + (tN + sadj[e]) * GPW;
        const uint64_t* w1p64 = (const uint64_t*)w1p;
        float partial = 0.0f;
        for (int m = q; m < 200; m += 16) {
            uint64_t mac = pk2(b1s[m] + Grow[m], 0.0f);
#pragma unroll
            for (int d2 = 0; d2 < 16; d2++)
                ffma2(mac, vp[d2], w1p64[d2 * 200 + m]);
            partial = fmaf(w2s[m], fmaxf(hadd2(mac), 0.0f), partial);
        }
#pragma unroll
        for (int off = 8; off > 0; off >>= 1)
            partial += __shfl_xor_sync(0xffffffffu, partial, off);
        if (q == 0) svals[e] = partial + __ldg(b2);
    }
    __syncthreads();

    if (tid == 0) {
        float mx = svals[0];
#pragma unroll
        for (int e = 1; e < EE; e++) mx = fmaxf(mx, svals[e]);
        float s = 0.0f;
#pragma unroll
        for (int e = 0; e < EE; e++) { float v = __expf(svals[e] - mx); satt[e] = v; s += v; }
        float inv = 1.0f / s;
#pragma unroll
        for (int e = 0; e < EE; e++) satt[e] *= inv;
    }
    __syncthreads();

    if (tid < 32) {
        float acc = 0.0f;
#pragma unroll
        for (int e = 0; e < EE; e++) acc = fmaf(satt[e], vc[e * 32 + tid], acc);
        hgv_s[tid] = acc;
    }
    __syncthreads();

    // hgX[g] = sum_e att_e * P[t,a_e,g] + sum_l wihp[l][g] * hgv[l]
    if (tid < 128) {
        int g = tid;
        float acc = 0.0f;
#pragma unroll
        for (int e = 0; e < EE; e++)
            acc = fmaf(satt[e], d_GP[(tN + sadj[e]) * GPW + 200 + g], acc);
#pragma unroll
        for (int l = 0; l < 32; l++)
            acc = fmaf(wihp[l * 128 + g], hgv_s[l], acc);
        d_hgX[bid * 128 + g] = acc;
    }
}

// ===========================================================================
// K4: second LSTM + heads. Input gates precomputed in hgX.
// ===========================================================================
__global__ __launch_bounds__(128) void k_lstm2(
    const float* __restrict__ Whh2,
    const float* __restrict__ bih2, const float* __restrict__ bhh2,
    const float* __restrict__ Wf1, const float* __restrict__ bf1,
    const float* __restrict__ Wf2, const float* __restrict__ bf2,
    float* __restrict__ out)
{
    __shared__ float whs[128 * 33];
    int tid = threadIdx.x;
    for (int idx = tid; idx < 4096; idx += 128)
        whs[(idx >> 5) * 33 + (idx & 31)] = Whh2[idx];
    __syncthreads();

    int warp = (blockIdx.x * blockDim.x + tid) >> 5;
    int lane = tid & 31;
    if (warp >= NS) return;
    int n = warp;

    float bi = bih2[lane]      + bhh2[lane];
    float bf = bih2[32 + lane] + bhh2[32 + lane];
    float bg = bih2[64 + lane] + bhh2[64 + lane];
    float bo = bih2[96 + lane] + bhh2[96 + lane];

    float whi[32], whf[32], whg[32], who[32];
#pragma unroll
    for (int l = 0; l < 32; l++) {
        whi[l] = whs[lane * 33 + l];
        whf[l] = whs[(32 + lane) * 33 + l];
        whg[l] = whs[(64 + lane) * 33 + l];
        who[l] = whs[(96 + lane) * 33 + l];
    }

    float h = 0.0f, c = 0.0f;
#pragma unroll
    for (int t = 0; t < TT; t++) {
        const float* hx = d_hgX + (t * NS + n) * 128;
        float zi = bi + hx[lane];
        float zf = bf + hx[32 + lane];
        float zg = bg + hx[64 + lane];
        float zo = bo + hx[96 + lane];
#pragma unroll
        for (int l = 0; l < 32; l++) {
            float hl = __shfl_sync(0xffffffffu, h, l);
            zi = fmaf(whi[l], hl, zi);
            zf = fmaf(whf[l], hl, zf);
            zg = fmaf(whg[l], hl, zg);
            zo = fmaf(who[l], hl, zo);
        }
        c = sigf(zf) * c + sigf(zi) * tanhf(zg);
        h = sigf(zo) * tanhf(c);
    }

    float f1a = bf1[lane], f1b = bf1[32 + lane];
#pragma unroll
    for (int l = 0; l < 32; l++) {
        float hl = __shfl_sync(0xffffffffu, h, l);
        f1a = fmaf(Wf1[lane * 32 + l], hl, f1a);
        f1b = fmaf(Wf1[(32 + lane) * 32 + l], hl, f1b);
    }
    float p0 = Wf2[lane] * f1a + Wf2[32 + lane] * f1b;
    float p1 = Wf2[64 + lane] * f1a + Wf2[96 + lane] * f1b;
#pragma unroll
    for (int off = 16; off > 0; off >>= 1) {
        p0 += __shfl_xor_sync(0xffffffffu, p0, off);
        p1 += __shfl_xor_sync(0xffffffffu, p1, off);
    }
    if (lane == 0) {
        out[n * 2]     = p0 + bf2[0];
        out[n * 2 + 1] = p1 + bf2[1];
    }
}

// ===========================================================================
extern "C" void kernel_launch(void* const* d_in, const int* in_sizes, int n_in,
                              void* d_out, int out_size)
{
    const float* prices    = (const float*)d_in[0];
    const float* node_embs = (const float*)d_in[1];
    const int*   adj       = (const int*)  d_in[2];
    const int*   mem       = (const int*)  d_in[3];
    const float* W_ih1 = (const float*)d_in[4];
    const float* W_hh1 = (const float*)d_in[5];
    const float* b_ih1 = (const float*)d_in[6];
    const float* b_hh1 = (const float*)d_in[7];
    const float* Wt    = (const float*)d_in[8];
    const float* bt    = (const float*)d_in[9];
    const float* wk    = (const float*)d_in[10];
    const float* bk    = (const float*)d_in[11];
    const float* W1    = (const float*)d_in[12];
    const float* b1    = (const float*)d_in[13];
    const float* W2    = (const float*)d_in[14];
    const float* b2    = (const float*)d_in[15];
    const float* W_ih2 = (const float*)d_in[16];
    const float* W_hh2 = (const float*)d_in[17];
    const float* b_ih2 = (const float*)d_in[18];
    const float* b_hh2 = (const float*)d_in[19];
    const float* Wf1   = (const float*)d_in[20];
    const float* bf1   = (const float*)d_in[21];
    const float* Wf2   = (const float*)d_in[22];
    const float* bf2   = (const float*)d_in[23];
    float* out = (float*)d_out;

    const int mid_smem  = AT2_TOTAL * 4;  // 103040 B
    const int edge_smem = E_TOTAL * 4;    // 50048 B
    cudaFuncSetAttribute(k_mid2,  cudaFuncAttributeMaxDynamicSharedMemorySize, mid_smem);
    cudaFuncSetAttribute(k_edge2, cudaFuncAttributeMaxDynamicSharedMemorySize, edge_smem);

    k_lstm1<<<126, 128>>>(prices, W_ih1, W_hh1, b_ih1, b_hh1, W1, W_ih2);
    k_mid2<<<ATTN_BLKS + 192, 256, mid_smem>>>(adj, mem, Wt, bt, wk, node_embs, W1, W_ih2);
    k_edge2<<<TN, 256, edge_smem>>>(adj, mem, bk, b1, W2, b2);
    k_lstm2<<<125, 128>>>(W_hh2, b_ih2, b_hh2, Wf1, bf1, Wf2, bf2, out);
}

// round 15
// speedup vs baseline: 1.3394x; 1.0091x over previous
#include <cuda_runtime.h>
#include <cstdint>

// ---------------------------------------------------------------------------
// StockModel: T=4, N=500, E=16, K=32, H=32, D=768, ZD=800, EH=200
//
//  K1  k_lstm1: prices -> p_seq; block 125 packs W1a -> d_w1p, Wih2a -> d_wihp
//  K2  k_mid2:  blocks [0,192):  GEMM GP = node_embs @ [W1b|Wih2b]
//               blocks [192,692): vertex-conv attention -> d_alpha
//               (GEMM first so it overlaps attn instead of tailing it)
//  K3  k_edge2: per (t,n): fused gather+vc, scores (f32x2), att,
//               hgX = att*P + Wih2a@hgv -> d_hgX
//  K4  k_lstm2: gates = hgX + Whh2*h -> h_n -> out (N,2)
// ---------------------------------------------------------------------------

#define TT 4
#define NS 500
#define EE 16
#define KK 32
#define HH 32
#define DD 768
#define ZDIM 800
#define GPW 328
#define TN 2000
#define NROWS (TN * EE)

__device__ float d_pseq[TN * HH];
__device__ float d_GP[TN * GPW];
__device__ float d_alpha[NROWS * KK];
__device__ float d_hgX[TN * 128];
__device__ float d_w1p[32 * 200];    // W1[:, :32] pair-packed
__device__ float d_wihp[32 * 128];   // Wih2[:, :32] transposed: [l][g]

__device__ __forceinline__ float sigf(float x) { return 1.0f / (1.0f + __expf(-x)); }

// ---- packed f32x2 helpers (sm_100+) ----
__device__ __forceinline__ uint64_t pk2(float lo, float hi) {
    uint64_t r; asm("mov.b64 %0, {%1, %2};" : "=l"(r) : "f"(lo), "f"(hi)); return r;
}
__device__ __forceinline__ void ffma2(uint64_t& d, uint64_t a, uint64_t b) {
    asm("fma.rn.f32x2 %0, %1, %2, %3;" : "=l"(d) : "l"(a), "l"(b), "l"(d));
}
__device__ __forceinline__ float hadd2(uint64_t v) {
    float lo, hi; asm("mov.b64 {%0, %1}, %2;" : "=f"(lo), "=f"(hi) : "l"(v));
    return lo + hi;
}

// ---- cp.async helpers ----
__device__ __forceinline__ void cp16(uint32_t dst, const void* src) {
    asm volatile("cp.async.cg.shared.global [%0], [%1], 16;" :: "r"(dst), "l"(src) : "memory");
}
__device__ __forceinline__ void cp_commit() { asm volatile("cp.async.commit_group;" ::: "memory"); }
template<int N> __device__ __forceinline__ void cp_wait() {
    asm volatile("cp.async.wait_group %0;" :: "n"(N) : "memory");
}

// ===========================================================================
// K1: price LSTM (blocks 0..124), weight packs (block 125).
// ===========================================================================
__global__ __launch_bounds__(128) void k_lstm1(
    const float* __restrict__ prices,
    const float* __restrict__ Wih, const float* __restrict__ Whh,
    const float* __restrict__ bih, const float* __restrict__ bhh,
    const float* __restrict__ W1, const float* __restrict__ Wih2)
{
    int tid = threadIdx.x;
    if (blockIdx.x == 125) {
        for (int idx = tid; idx < 6400; idx += 128) {
            int pairIdx = idx >> 1, c = idx & 1;
            int d2 = pairIdx / 200, m = pairIdx % 200;
            d_w1p[idx] = W1[m * ZDIM + 2 * d2 + c];
        }
        for (int idx = tid; idx < 4096; idx += 128) {
            int l = idx >> 7, g = idx & 127;
            d_wihp[idx] = Wih2[g * ZDIM + l];
        }
        return;
    }

    __shared__ float whs[128 * 33];
    for (int idx = tid; idx < 4096; idx += 128)
        whs[(idx >> 5) * 33 + (idx & 31)] = Whh[idx];
    __syncthreads();

    int warp = (blockIdx.x * blockDim.x + tid) >> 5;
    int lane = tid & 31;
    if (warp >= NS) return;
    int n = warp;

    float wxi = Wih[lane],      wxf = Wih[32 + lane];
    float wxg = Wih[64 + lane], wxo = Wih[96 + lane];
    float bi = bih[lane]      + bhh[lane];
    float bf = bih[32 + lane] + bhh[32 + lane];
    float bg = bih[64 + lane] + bhh[64 + lane];
    float bo = bih[96 + lane] + bhh[96 + lane];

    float whi[32], whf[32], whg[32], who[32];
#pragma unroll
    for (int l = 0; l < 32; l++) {
        whi[l] = whs[lane * 33 + l];
        whf[l] = whs[(32 + lane) * 33 + l];
        whg[l] = whs[(64 + lane) * 33 + l];
        who[l] = whs[(96 + lane) * 33 + l];
    }

    float h = 0.0f, c = 0.0f;
#pragma unroll
    for (int t = 0; t < TT; t++) {
        float x = prices[t * NS + n];
        float zi = fmaf(wxi, x, bi), zf = fmaf(wxf, x, bf);
        float zg = fmaf(wxg, x, bg), zo = fmaf(wxo, x, bo);
#pragma unroll
        for (int l = 0; l < 32; l++) {
            float hl = __shfl_sync(0xffffffffu, h, l);
            zi = fmaf(whi[l], hl, zi);
            zf = fmaf(whf[l], hl, zf);
            zg = fmaf(whg[l], hl, zg);
            zo = fmaf(who[l], hl, zo);
        }
        c = sigf(zf) * c + sigf(zi) * tanhf(zg);
        h = sigf(zo) * tanhf(c);
        d_pseq[(t * NS + n) * HH + lane] = h;
    }
}

// ===========================================================================
// K2: fused GEMM (blocks 0..191) + attn (blocks 192..691).
// ===========================================================================
#define AT2_WT    0        // 4096  wt[q][j][d]
#define AT2_BT    4096     // 1024
#define AT2_WK    5120     // 32
#define AT2_ADJ   5152     // 64 ints
#define AT2_TN    5216     // 64 ints
#define AT2_MIDX  5280     // 2048 ints
#define AT2_SROWS 7328     // 2 x 256 x 36 = 18432
#define AT2_TOTAL 25760    // = 103040 bytes
#define GEMM_BLKS 192

__global__ __launch_bounds__(256, 2) void k_mid2(
    const int* __restrict__ adj, const int* __restrict__ mem,
    const float* __restrict__ Wt, const float* __restrict__ bt,
    const float* __restrict__ wk,
    const float* __restrict__ ne,
    const float* __restrict__ W1,
    const float* __restrict__ Wih2)
{
    extern __shared__ float dyn[];
    int tid = threadIdx.x;

    if (blockIdx.x >= GEMM_BLKS) {
        // -------- attention part --------
        int abid = blockIdx.x - GEMM_BLKS;     // 0..499
        float* btA   = dyn + AT2_BT;
        float* wkA   = dyn + AT2_WK;
        int*   sadj  = (int*)(dyn + AT2_ADJ);
        int*   stN   = (int*)(dyn + AT2_TN);
        int*   midx  = (int*)(dyn + AT2_MIDX);
        uint32_t sbase = (uint32_t)__cvta_generic_to_shared(dyn);

        int rloc = tid & 63, q = tid >> 6;
        int w = tid >> 5, lane = tid & 31;
        int cg = lane >> 3, cb = lane & 7;

        if (tid < 64) {
            int row = abid * 64 + tid;
            int tn = row >> 4, e = row & 15;
            sadj[tid] = adj[tn * EE + e];
            stN[tid]  = (tn / NS) * NS;
        }
        for (int idx = tid; idx < 1024; idx += 256) btA[idx] = bt[idx];
        if (tid < 32) wkA[tid] = wk[tid];
        __syncthreads();
        for (int idx = tid; idx < 2048; idx += 256) {
            int r = idx >> 5, i = idx & 31;
            midx[idx] = stN[r] + mem[(stN[r] + sadj[r]) * KK + i];
        }
        __syncthreads();

        // prologue: stage srows for step 0 into buffer 0
        {
#pragma unroll
            for (int rr = 0; rr < 8; rr++) {
                int r = w * 32 + rr * 4 + cg;
                int rl = r & 63, qq2 = r >> 6;
                int mrow = midx[rl * 32 + 8 * qq2];
                cp16(sbase + (AT2_SROWS + r * 36 + cb * 4) * 4,
                     d_pseq + mrow * 32 + cb * 4);
            }
            cp_commit();
        }

        float acc[32];
#pragma unroll
        for (int j = 0; j < 32; j++) acc[j] = 0.0f;

        for (int s = 0; s < 8; s++) {
            int i = 8 * q + s;
            // wt(s): synchronous group (L2-resident, cheap)
            {
                const float* wsrc = Wt + i * 1024 + rloc * 16;
                uint32_t wd = sbase + (AT2_WT + q * 1024 + rloc * 16) * 4;
                cp16(wd, wsrc); cp16(wd + 16, wsrc + 4);
                cp16(wd + 32, wsrc + 8); cp16(wd + 48, wsrc + 12);
                cp_commit();
            }
            // srows(s+1): pipelined group
            if (s < 7) {
                int bsel = (s + 1) & 1;
#pragma unroll
                for (int rr = 0; rr < 8; rr++) {
                    int r = w * 32 + rr * 4 + cg;
                    int rl = r & 63, qq2 = r >> 6;
                    int mrow = midx[rl * 32 + 8 * qq2 + s + 1];
                    cp16(sbase + (AT2_SROWS + bsel * 9216 + r * 36 + cb * 4) * 4,
                         d_pseq + mrow * 32 + cb * 4);
                }
                cp_commit();
                cp_wait<1>();
            } else {
                cp_wait<0>();
            }
            __syncthreads();

            uint64_t rgp[16];
            {
                const float4* basep =
                    (const float4*)(dyn + AT2_SROWS + (s & 1) * 9216 + (q * 64 + rloc) * 36);
#pragma unroll
                for (int u = 0; u < 8; u++) {
                    float4 rv = basep[u];
                    rgp[2 * u]     = pk2(rv.x, rv.y);
                    rgp[2 * u + 1] = pk2(rv.z, rv.w);
                }
            }
            const float* wb = dyn + AT2_WT + q * 1024;
            float em[32];
            float srow = 0.0f;
#pragma unroll
            for (int j = 0; j < 32; j++) {
                const ulonglong2* w2p = (const ulonglong2*)(wb + j * 32);
                // dual 8-deep FFMA2 chains (halved RAW exposure)
                uint64_t mac0 = pk2(btA[i * 32 + j], 0.0f);
                uint64_t mac1 = pk2(0.0f, 0.0f);
#pragma unroll
                for (int u = 0; u < 8; u++) {
                    ulonglong2 wv = w2p[u];
                    ffma2(mac0, wv.x, rgp[2 * u]);
                    ffma2(mac1, wv.y, rgp[2 * u + 1]);
                }
                float ev = __expf(hadd2(mac0) + hadd2(mac1));
                em[j] = ev;
                srow += ev;
            }
            float f = __fdividef(wkA[i], srow);
#pragma unroll
            for (int j = 0; j < 32; j++) acc[j] = fmaf(em[j], f, acc[j]);
            __syncthreads();
        }

        // cross-quarter reduction (red overlays srows)
        float* red = dyn + AT2_SROWS;
        {
            float4* rp = (float4*)(red + q * 2048 + rloc * 32);
#pragma unroll
            for (int u = 0; u < 8; u++)
                rp[u] = make_float4(acc[u * 4], acc[u * 4 + 1], acc[u * 4 + 2], acc[u * 4 + 3]);
        }
        __syncthreads();
        for (int o = tid; o < 512; o += 256) {
            const float4 v0 = *(const float4*)(red + o * 4);
            const float4 v1 = *(const float4*)(red + 2048 + o * 4);
            const float4 v2 = *(const float4*)(red + 4096 + o * 4);
            const float4 v3 = *(const float4*)(red + 6144 + o * 4);
            float4 v = make_float4(v0.x + v1.x + v2.x + v3.x,
                                   v0.y + v1.y + v2.y + v3.y,
                                   v0.z + v1.z + v2.z + v3.z,
                                   v0.w + v1.w + v2.w + v3.w);
            *(float4*)(d_alpha + abid * 2048 + o * 4) = v;
        }
    } else {
        // -------- GEMM part: GP = ne(2000x768) @ B(768x328) --------
        float* As = dyn;          // 16*64
        float* Bs = dyn + 1024;   // 16*64
        int bx = blockIdx.x;
        int rb = (bx & 31) * 64, cb2 = (bx >> 5) * 64;
        int tx = tid & 15, ty = tid >> 4;
        int lm = tid >> 2;
        int lk = (tid & 3) * 4;

        float acc[4][4];
#pragma unroll
        for (int r = 0; r < 4; r++)
#pragma unroll
            for (int cq = 0; cq < 4; cq++) acc[r][cq] = 0.0f;

        int arow = rb + lm;
        int bcol = cb2 + lm;

        for (int k0 = 0; k0 < DD; k0 += 16) {
            float4 av = make_float4(0.f, 0.f, 0.f, 0.f);
            if (arow < TN) av = *(const float4*)(ne + arow * DD + k0 + lk);
            float4 bv = make_float4(0.f, 0.f, 0.f, 0.f);
            if (bcol < 200)      bv = *(const float4*)(W1 + bcol * ZDIM + 32 + k0 + lk);
            else if (bcol < GPW) bv = *(const float4*)(Wih2 + (bcol - 200) * ZDIM + 32 + k0 + lk);
            As[(lk + 0) * 64 + lm] = av.x; As[(lk + 1) * 64 + lm] = av.y;
            As[(lk + 2) * 64 + lm] = av.z; As[(lk + 3) * 64 + lm] = av.w;
            Bs[(lk + 0) * 64 + lm] = bv.x; Bs[(lk + 1) * 64 + lm] = bv.y;
            Bs[(lk + 2) * 64 + lm] = bv.z; Bs[(lk + 3) * 64 + lm] = bv.w;
            __syncthreads();
#pragma unroll
            for (int k = 0; k < 16; k++) {
                float4 a4 = *(const float4*)(&As[k * 64 + ty * 4]);
                float4 b4 = *(const float4*)(&Bs[k * 64 + tx * 4]);
                float ar[4] = {a4.x, a4.y, a4.z, a4.w};
                float br[4] = {b4.x, b4.y, b4.z, b4.w};
#pragma unroll
                for (int r = 0; r < 4; r++)
#pragma unroll
                    for (int cq = 0; cq < 4; cq++)
                        acc[r][cq] = fmaf(ar[r], br[cq], acc[r][cq]);
            }
            __syncthreads();
        }
#pragma unroll
        for (int r = 0; r < 4; r++) {
            int rrow = rb + ty * 4 + r;
            int col = cb2 + tx * 4;
            if (rrow < TN && col < GPW) {
                float4 v = make_float4(acc[r][0], acc[r][1], acc[r][2], acc[r][3]);
                *(float4*)(d_GP + rrow * GPW + col) = v;
            }
        }
    }
}

// ===========================================================================
// K3: per (t,n): fused gather+vc, scores (f32x2), att, hgX. smem 50KB.
// ===========================================================================
#define E_W1P    0         // 6400
#define E_WIHP   6400      // 4096
#define E_ALPHA  10496     // 512
#define E_VC     11008     // 512
#define E_B1S    11520     // 200
#define E_W2S    11720     // 200
#define E_SVALS  11920     // 16
#define E_SATT   11936     // 16
#define E_HGV    11952     // 32
#define E_SADJ   11984     // 16 ints
#define E_MIDX   12000     // 512 ints
#define E_TOTAL  12512     // floats = 50048 B

__global__ __launch_bounds__(256, 4) void k_edge2(
    const int* __restrict__ adj, const int* __restrict__ mem,
    const float* __restrict__ bk,
    const float* __restrict__ b1,
    const float* __restrict__ W2, const float* __restrict__ b2)
{
    extern __shared__ float sm[];
    float* w1p    = sm + E_W1P;
    float* wihp   = sm + E_WIHP;
    float* alpha  = sm + E_ALPHA;
    float* vc     = sm + E_VC;
    float* b1s    = sm + E_B1S;
    float* w2s    = sm + E_W2S;
    float* svals  = sm + E_SVALS;
    float* satt   = sm + E_SATT;
    float* hgv_s  = sm + E_HGV;
    int*   sadj   = (int*)(sm + E_SADJ);
    int*   midx   = (int*)(sm + E_MIDX);

    int tid = threadIdx.x, w = tid >> 5, lane = tid & 31;
    int bid = blockIdx.x;
    int tN  = (bid / NS) * NS;

    if (tid < EE) sadj[tid] = adj[bid * EE + tid];
    for (int q = tid; q < 512; q += 256) alpha[q] = d_alpha[bid * 512 + q];
    {
        const float4* src = (const float4*)d_w1p;
        float4* dst = (float4*)w1p;
        for (int idx = tid; idx < 1600; idx += 256) dst[idx] = src[idx];
        const float4* src2 = (const float4*)d_wihp;
        float4* dst2 = (float4*)wihp;
        for (int idx = tid; idx < 1024; idx += 256) dst2[idx] = src2[idx];
    }
    if (tid < 200) { b1s[tid] = b1[tid]; w2s[tid] = W2[tid]; }
    __syncthreads();

    for (int q = tid; q < EE * KK; q += 256)
        midx[q] = tN + mem[(tN + sadj[q >> 5]) * KK + (q & 31)];
    __syncthreads();

    // fused gather + vc: warp w handles edges {w, w+8}; lane = d
    float bk0 = __ldg(bk);
#pragma unroll
    for (int eo = 0; eo < 2; eo++) {
        int e = w + eo * 8;
        float acc = bk0;
#pragma unroll
        for (int j = 0; j < 32; j++) {
            int row = midx[e * 32 + j];
            float a = alpha[e * 32 + j];
            acc = fmaf(a, d_pseq[row * 32 + lane], acc);
        }
        vc[e * 32 + lane] = acc;
    }
    __syncthreads();

    // ---- edge scores: 16 threads/edge; dual FFMA2 chains over d ----
    {
        int e = tid >> 4, q = tid & 15;
        uint64_t vp[16];
#pragma unroll
        for (int d2 = 0; d2 < 16; d2++)
            vp[d2] = pk2(vc[e * 32 + 2 * d2], vc[e * 32 + 2 * d2 + 1]);
        const float* Grow = d_GP + (tN + sadj[e]) * GPW;
        const uint64_t* w1p64 = (const uint64_t*)w1p;
        float partial = 0.0f;
        for (int m = q; m < 200; m += 16) {
            uint64_t mac0 = pk2(b1s[m] + Grow[m], 0.0f);
            uint64_t mac1 = pk2(0.0f, 0.0f);
#pragma unroll
            for (int d2 = 0; d2 < 8; d2++) {
                ffma2(mac0, vp[2 * d2],     w1p64[(2 * d2) * 200 + m]);
                ffma2(mac1, vp[2 * d2 + 1], w1p64[(2 * d2 + 1) * 200 + m]);
            }
            partial = fmaf(w2s[m], fmaxf(hadd2(mac0) + hadd2(mac1), 0.0f), partial);
        }
#pragma unroll
        for (int off = 8; off > 0; off >>= 1)
            partial += __shfl_xor_sync(0xffffffffu, partial, off);
        if (q == 0) svals[e] = partial + __ldg(b2);
    }
    __syncthreads();

    if (tid == 0) {
        float mx = svals[0];
#pragma unroll
        for (int e = 1; e < EE; e++) mx = fmaxf(mx, svals[e]);
        float s = 0.0f;
#pragma unroll
        for (int e = 0; e < EE; e++) { float v = __expf(svals[e] - mx); satt[e] = v; s += v; }
        float inv = 1.0f / s;
#pragma unroll
        for (int e = 0; e < EE; e++) satt[e] *= inv;
    }
    __syncthreads();

    if (tid < 32) {
        float acc = 0.0f;
#pragma unroll
        for (int e = 0; e < EE; e++) acc = fmaf(satt[e], vc[e * 32 + tid], acc);
        hgv_s[tid] = acc;
    }
    __syncthreads();

    // hgX[g] = sum_e att_e * P[t,a_e,g] + sum_l wihp[l][g] * hgv[l]
    if (tid < 128) {
        int g = tid;
        float acc = 0.0f;
#pragma unroll
        for (int e = 0; e < EE; e++)
            acc = fmaf(satt[e], d_GP[(tN + sadj[e]) * GPW + 200 + g], acc);
#pragma unroll
        for (int l = 0; l < 32; l++)
            acc = fmaf(wihp[l * 128 + g], hgv_s[l], acc);
        d_hgX[bid * 128 + g] = acc;
    }
}

// ===========================================================================
// K4: second LSTM + heads. Input gates precomputed in hgX.
// ===========================================================================
__global__ __launch_bounds__(128) void k_lstm2(
    const float* __restrict__ Whh2,
    const float* __restrict__ bih2, const float* __restrict__ bhh2,
    const float* __restrict__ Wf1, const float* __restrict__ bf1,
    const float* __restrict__ Wf2, const float* __restrict__ bf2,
    float* __restrict__ out)
{
    __shared__ float whs[128 * 33];
    int tid = threadIdx.x;
    for (int idx = tid; idx < 4096; idx += 128)
        whs[(idx >> 5) * 33 + (idx & 31)] = Whh2[idx];
    __syncthreads();

    int warp = (blockIdx.x * blockDim.x + tid) >> 5;
    int lane = tid & 31;
    if (warp >= NS) return;
    int n = warp;

    float bi = bih2[lane]      + bhh2[lane];
    float bf = bih2[32 + lane] + bhh2[32 + lane];
    float bg = bih2[64 + lane] + bhh2[64 + lane];
    float bo = bih2[96 + lane] + bhh2[96 + lane];

    float whi[32], whf[32], whg[32], who[32];
#pragma unroll
    for (int l = 0; l < 32; l++) {
        whi[l] = whs[lane * 33 + l];
        whf[l] = whs[(32 + lane) * 33 + l];
        whg[l] = whs[(64 + lane) * 33 + l];
        who[l] = whs[(96 + lane) * 33 + l];
    }

    float h = 0.0f, c = 0.0f;
#pragma unroll
    for (int t = 0; t < TT; t++) {
        const float* hx = d_hgX + (t * NS + n) * 128;
        float zi = bi + hx[lane];
        float zf = bf + hx[32 + lane];
        float zg = bg + hx[64 + lane];
        float zo = bo + hx[96 + lane];
#pragma unroll
        for (int l = 0; l < 32; l++) {
            float hl = __shfl_sync(0xffffffffu, h, l);
            zi = fmaf(whi[l], hl, zi);
            zf = fmaf(whf[l], hl, zf);
            zg = fmaf(whg[l], hl, zg);
            zo = fmaf(who[l], hl, zo);
        }
        c = sigf(zf) * c + sigf(zi) * tanhf(zg);
        h = sigf(zo) * tanhf(c);
    }

    float f1a = bf1[lane], f1b = bf1[32 + lane];
#pragma unroll
    for (int l = 0; l < 32; l++) {
        float hl = __shfl_sync(0xffffffffu, h, l);
        f1a = fmaf(Wf1[lane * 32 + l], hl, f1a);
        f1b = fmaf(Wf1[(32 + lane) * 32 + l], hl, f1b);
    }
    float p0 = Wf2[lane] * f1a + Wf2[32 + lane] * f1b;
    float p1 = Wf2[64 + lane] * f1a + Wf2[96 + lane] * f1b;
#pragma unroll
    for (int off = 16; off > 0; off >>= 1) {
        p0 += __shfl_xor_sync(0xffffffffu, p0, off);
        p1 += __shfl_xor_sync(0xffffffffu, p1, off);
    }
    if (lane == 0) {
        out[n * 2]     = p0 + bf2[0];
        out[n * 2 + 1] = p1 + bf2[1];
    }
}

// ===========================================================================
extern "C" void kernel_launch(void* const* d_in, const int* in_sizes, int n_in,
                              void* d_out, int out_size)
{
    const float* prices    = (const float*)d_in[0];
    const float* node_embs = (const float*)d_in[1];
    const int*   adj       = (const int*)  d_in[2];
    const int*   mem       = (const int*)  d_in[3];
    const float* W_ih1 = (const float*)d_in[4];
    const float* W_hh1 = (const float*)d_in[5];
    const float* b_ih1 = (const float*)d_in[6];
    const float* b_hh1 = (const float*)d_in[7];
    const float* Wt    = (const float*)d_in[8];
    const float* bt    = (const float*)d_in[9];
    const float* wk    = (const float*)d_in[10];
    const float* bk    = (const float*)d_in[11];
    const float* W1    = (const float*)d_in[12];
    const float* b1    = (const float*)d_in[13];
    const float* W2    = (const float*)d_in[14];
    const float* b2    = (const float*)d_in[15];
    const float* W_ih2 = (const float*)d_in[16];
    const float* W_hh2 = (const float*)d_in[17];
    const float* b_ih2 = (const float*)d_in[18];
    const float* b_hh2 = (const float*)d_in[19];
    const float* Wf1   = (const float*)d_in[20];
    const float* bf1   = (const float*)d_in[21];
    const float* Wf2   = (const float*)d_in[22];
    const float* bf2   = (const float*)d_in[23];
    float* out = (float*)d_out;

    const int mid_smem  = AT2_TOTAL * 4;  // 103040 B
    const int edge_smem = E_TOTAL * 4;    // 50048 B
    cudaFuncSetAttribute(k_mid2,  cudaFuncAttributeMaxDynamicSharedMemorySize, mid_smem);
    cudaFuncSetAttribute(k_edge2, cudaFuncAttributeMaxDynamicSharedMemorySize, edge_smem);

    k_lstm1<<<126, 128>>>(prices, W_ih1, W_hh1, b_ih1, b_hh1, W1, W_ih2);
    k_mid2<<<GEMM_BLKS + 500, 256, mid_smem>>>(adj, mem, Wt, bt, wk, node_embs, W1, W_ih2);
    k_edge2<<<TN, 256, edge_smem>>>(adj, mem, bk, b1, W2, b2);
    k_lstm2<<<125, 128>>>(W_hh2, b_ih2, b_hh2, Wf1, bf1, Wf2, bf2, out);
}